// round 1
// baseline (speedup 1.0000x reference)
#include <cuda_runtime.h>
#include <math.h>

// ---------------- problem constants ----------------
constexpr int B_   = 2;
constexpr int S_   = 2048;
constexpr int HQ_  = 32;
constexpr int HK_  = 8;
constexpr int D_   = 128;
constexpr int G_   = 4;       // HQ/HK
constexpr int W_   = 1024;    // window
constexpr int NTOK = B_ * S_;

// ---------------- scratch (static device globals; no runtime alloc) -------
__device__ float g_qrope[(size_t)NTOK * HQ_ * D_];   // 64 MB
__device__ float g_krope[(size_t)NTOK * HK_ * D_];   // 16 MB

// ---------------- RoPE kernel ----------------
__global__ void rope_kernel(const float* __restrict__ q,
                            const float* __restrict__ k,
                            const int*   __restrict__ pos) {
    int idx = blockIdx.x * blockDim.x + threadIdx.x;
    const int NQ = NTOK * HQ_ * (D_ / 2);
    const int NK = NTOK * HK_ * (D_ / 2);
    if (idx >= NQ + NK) return;
    bool isQ = idx < NQ;
    int i = isQ ? idx : idx - NQ;
    int d  = i & 63;          // half-dim index 0..63
    int rh = i >> 6;
    int H  = isQ ? HQ_ : HK_;
    int h  = rh % H;
    int t  = rh / H;          // global token 0..NTOK-1

    // inv_freq computed in double then rounded -> matches fp32 reference closely
    float inv = (float)pow(10000.0, -(double)d / 64.0);
    float ang = (float)pos[t] * inv;     // fp32 multiply, like the reference
    float sv, cv;
    sincosf(ang, &sv, &cv);              // accurate range-reduced version

    const float* src = isQ ? q : k;
    float* dst = isQ ? g_qrope : g_krope;
    size_t base = ((size_t)t * H + h) * D_ + d;
    float x1 = src[base];
    float x2 = src[base + 64];
    dst[base]      = x1 * cv - x2 * sv;
    dst[base + 64] = x2 * cv + x1 * sv;
}

// ---------------- attention kernel ----------------
constexpr int TQ   = 32;            // query positions per block
constexpr int TK   = 64;            // keys per smem tile
constexpr int ROWS = TQ * G_;       // 128 q-rows (row = qi*4 + g)

constexpr int QSTR = 132;           // padded strides (floats)
constexpr int KSTR = 132;
constexpr int VSTR = 128;
constexpr int PSTR = 65;

constexpr int SM_Q = 0;
constexpr int SM_K = SM_Q + ROWS * QSTR;   // 16896
constexpr int SM_V = SM_K + TK   * KSTR;   // 25344
constexpr int SM_P = SM_V + TK   * VSTR;   // 33536
constexpr int SM_M = SM_P + ROWS * PSTR;   // 41856
constexpr int SM_L = SM_M + ROWS;          // 41984
constexpr int SM_A = SM_L + ROWS;          // 42112
constexpr int SMEM_FLOATS = SM_A + ROWS;   // 42240
constexpr int SMEM_BYTES  = SMEM_FLOATS * 4;   // 168960 B

__global__ void __launch_bounds__(256, 1)
attn_kernel(const float* __restrict__ value, float* __restrict__ out) {
    extern __shared__ float sm[];
    float* Qs = sm + SM_Q;
    float* Ks = sm + SM_K;
    float* Vs = sm + SM_V;
    float* Ps = sm + SM_P;
    float* Ms = sm + SM_M;
    float* Ls = sm + SM_L;
    float* As = sm + SM_A;

    const int tid = threadIdx.x;
    const int bid = blockIdx.x;
    const int qt = bid & 63;          // S_/TQ = 64
    const int hk = (bid >> 6) & 7;    // HK_ = 8
    const int b  = bid >> 9;
    const int q0 = qt * TQ;

    // ---- load Q tile: 128 rows x 128 d (row = qi*4 + g) ----
    for (int i = tid; i < ROWS * 32; i += 256) {
        int r = i >> 5, dd = i & 31;
        int qi = r >> 2, g = r & 3;
        float4 qv = *(const float4*)&g_qrope[
            (((size_t)(b * S_ + q0 + qi) * HQ_) + hk * G_ + g) * D_ + dd * 4];
        *(float4*)&Qs[r * QSTR + dd * 4] = qv;
    }
    if (tid < ROWS) { Ms[tid] = -1e30f; Ls[tid] = 0.f; }

    float4 acc[4][4];
    #pragma unroll
    for (int r = 0; r < 4; r++)
        #pragma unroll
        for (int i2 = 0; i2 < 4; i2++) acc[r][i2] = make_float4(0.f, 0.f, 0.f, 0.f);

    const int rg = tid >> 3;   // row-group 0..31 (rows rg*4..rg*4+3; qi == rg)
    const int lg = tid & 7;    // key-group (QK) / d-group (PV)

    const int imax = q0 + TQ - 1;
    int lo = q0 - (W_ - 1); if (lo < 0) lo = 0;
    const int kt0 = lo / TK, kt1 = imax / TK;

    for (int kt = kt0; kt <= kt1; ++kt) {
        const int k0 = kt * TK;
        __syncthreads();   // protect K/V smem from previous iteration's readers
        // ---- load K,V tile (coalesced) ----
        for (int i = tid; i < TK * 32; i += 256) {
            int kk = i >> 5, dd = i & 31;
            int j = k0 + kk;
            size_t kb = (((size_t)(b * S_ + j) * HK_) + hk) * D_ + dd * 4;
            *(float4*)&Ks[kk * KSTR + dd * 4] = *(const float4*)&g_krope[kb];
            *(float4*)&Vs[kk * VSTR + dd * 4] = *(const float4*)&value[kb];
        }
        __syncthreads();

        // ---- QK^T: thread owns 4 q-rows x 8 keys (keys lg + 8c) ----
        float s[4][8];
        #pragma unroll
        for (int r = 0; r < 4; r++)
            #pragma unroll
            for (int c = 0; c < 8; c++) s[r][c] = 0.f;

        for (int dd = 0; dd < 32; ++dd) {
            float4 qv[4];
            #pragma unroll
            for (int r = 0; r < 4; r++)
                qv[r] = *(const float4*)&Qs[(rg * 4 + r) * QSTR + dd * 4];
            #pragma unroll
            for (int c = 0; c < 8; c++) {
                float4 kv = *(const float4*)&Ks[(lg + 8 * c) * KSTR + dd * 4];
                #pragma unroll
                for (int r = 0; r < 4; r++) {
                    s[r][c] = fmaf(qv[r].x, kv.x, s[r][c]);
                    s[r][c] = fmaf(qv[r].y, kv.y, s[r][c]);
                    s[r][c] = fmaf(qv[r].z, kv.z, s[r][c]);
                    s[r][c] = fmaf(qv[r].w, kv.w, s[r][c]);
                }
            }
        }
        const float scale = 0.08838834764831845f;   // 1/sqrt(128)
        #pragma unroll
        for (int r = 0; r < 4; r++)
            #pragma unroll
            for (int c = 0; c < 8; c++)
                Ps[(rg * 4 + r) * PSTR + lg + 8 * c] = s[r][c] * scale;
        __syncthreads();

        // ---- online-softmax row pass (mask recomputed; robust to fully-masked tiles)
        if (tid < ROWS) {
            int i_abs = q0 + (tid >> 2);
            int jlo = i_abs - (W_ - 1) - k0; if (jlo < 0) jlo = 0;
            int jhi = i_abs - k0;            if (jhi > TK - 1) jhi = TK - 1;
            float mo = Ms[tid];
            float mx = mo;
            for (int kk2 = jlo; kk2 <= jhi; ++kk2)
                mx = fmaxf(mx, Ps[tid * PSTR + kk2]);
            float alpha = __expf(mo - mx);
            float l = Ls[tid] * alpha;
            for (int kk2 = 0; kk2 < TK; ++kk2) {
                float p = 0.f;
                if (kk2 >= jlo && kk2 <= jhi)
                    p = __expf(Ps[tid * PSTR + kk2] - mx);
                Ps[tid * PSTR + kk2] = p;
                l += p;
            }
            Ms[tid] = mx; Ls[tid] = l; As[tid] = alpha;
        }
        __syncthreads();

        // ---- rescale acc, then P@V: thread owns 4 q-rows x 16 d (d-f4 lg+8i)
        #pragma unroll
        for (int r = 0; r < 4; r++) {
            float al = As[rg * 4 + r];
            #pragma unroll
            for (int i2 = 0; i2 < 4; i2++) {
                acc[r][i2].x *= al; acc[r][i2].y *= al;
                acc[r][i2].z *= al; acc[r][i2].w *= al;
            }
        }
        for (int kk2 = 0; kk2 < TK; ++kk2) {
            float p[4];
            #pragma unroll
            for (int r = 0; r < 4; r++)
                p[r] = Ps[(rg * 4 + r) * PSTR + kk2];
            #pragma unroll
            for (int i2 = 0; i2 < 4; i2++) {
                float4 vv = *(const float4*)&Vs[kk2 * VSTR + (lg + 8 * i2) * 4];
                #pragma unroll
                for (int r = 0; r < 4; r++) {
                    acc[r][i2].x = fmaf(p[r], vv.x, acc[r][i2].x);
                    acc[r][i2].y = fmaf(p[r], vv.y, acc[r][i2].y);
                    acc[r][i2].z = fmaf(p[r], vv.z, acc[r][i2].z);
                    acc[r][i2].w = fmaf(p[r], vv.w, acc[r][i2].w);
                }
            }
        }
    }

    // ---- epilogue: out[(b,s), hq*D + d], hq = hk*G + g ----
    #pragma unroll
    for (int r = 0; r < 4; r++) {
        int row = rg * 4 + r;
        float invl = 1.f / Ls[row];
        int qi = row >> 2, g = row & 3;
        float* op = out + ((size_t)(b * S_ + q0 + qi) * (HQ_ * D_))
                        + (size_t)(hk * G_ + g) * D_;
        #pragma unroll
        for (int i2 = 0; i2 < 4; i2++) {
            float4 o;
            o.x = acc[r][i2].x * invl; o.y = acc[r][i2].y * invl;
            o.z = acc[r][i2].z * invl; o.w = acc[r][i2].w * invl;
            *(float4*)&op[(lg + 8 * i2) * 4] = o;
        }
    }
}

// ---------------- launcher ----------------
extern "C" void kernel_launch(void* const* d_in, const int* in_sizes, int n_in,
                              void* d_out, int out_size) {
    const float* q  = (const float*)d_in[0];
    const float* k  = (const float*)d_in[1];
    const float* v  = (const float*)d_in[2];
    const int*   ps = (const int*)d_in[3];
    float* out = (float*)d_out;

    // RoPE for Q and K into device scratch
    int total = NTOK * HQ_ * (D_ / 2) + NTOK * HK_ * (D_ / 2);
    rope_kernel<<<(total + 255) / 256, 256>>>(q, k, ps);

    // attention (168 KB dynamic smem)
    cudaFuncSetAttribute(attn_kernel,
                         cudaFuncAttributeMaxDynamicSharedMemorySize, SMEM_BYTES);
    int nblk = B_ * HK_ * (S_ / TQ);   // 1024
    attn_kernel<<<nblk, 256, SMEM_BYTES>>>(v, out);
}

// round 3
// speedup vs baseline: 1.1319x; 1.1319x over previous
#include <cuda_runtime.h>
#include <math.h>

// ---------------- problem constants ----------------
constexpr int B_   = 2;
constexpr int S_   = 2048;
constexpr int HQ_  = 32;
constexpr int HK_  = 8;
constexpr int D_   = 128;
constexpr int G_   = 4;       // HQ/HK
constexpr int W_   = 1024;    // window
constexpr int NTOK = B_ * S_;

using u64 = unsigned long long;

__device__ __forceinline__ u64 ffma2(u64 a, u64 b, u64 c) {
    u64 d; asm("fma.rn.f32x2 %0, %1, %2, %3;" : "=l"(d) : "l"(a), "l"(b), "l"(c));
    return d;
}
__device__ __forceinline__ u64 fmul2(u64 a, u64 b) {
    u64 d; asm("mul.rn.f32x2 %0, %1, %2;" : "=l"(d) : "l"(a), "l"(b));
    return d;
}
__device__ __forceinline__ u64 pack2(float x) {
    u64 d; asm("mov.b64 %0, {%1, %1};" : "=l"(d) : "f"(x));
    return d;
}
__device__ __forceinline__ float2 unpack2(u64 v) {
    float2 f; asm("mov.b64 {%0, %1}, %2;" : "=f"(f.x), "=f"(f.y) : "l"(v));
    return f;
}

// ---------------- scratch (static device globals; no runtime alloc) -------
__device__ float g_qrope[(size_t)NTOK * HQ_ * D_];   // 64 MB
__device__ float g_krope[(size_t)NTOK * HK_ * D_];   // 16 MB

// ---------------- RoPE kernel ----------------
__global__ void rope_kernel(const float* __restrict__ q,
                            const float* __restrict__ k,
                            const int*   __restrict__ pos) {
    int idx = blockIdx.x * blockDim.x + threadIdx.x;
    const int NQ = NTOK * HQ_ * (D_ / 2);
    const int NK = NTOK * HK_ * (D_ / 2);
    if (idx >= NQ + NK) return;
    bool isQ = idx < NQ;
    int i = isQ ? idx : idx - NQ;
    int d  = i & 63;          // half-dim index 0..63
    int rh = i >> 6;
    int H  = isQ ? HQ_ : HK_;
    int h  = rh % H;
    int t  = rh / H;          // global token 0..NTOK-1

    float inv = (float)pow(10000.0, -(double)d / 64.0);
    float ang = (float)pos[t] * inv;
    float sv, cv;
    sincosf(ang, &sv, &cv);

    const float* src = isQ ? q : k;
    float* dst = isQ ? g_qrope : g_krope;
    size_t base = ((size_t)t * H + h) * D_ + d;
    float x1 = src[base];
    float x2 = src[base + 64];
    dst[base]      = x1 * cv - x2 * sv;
    dst[base + 64] = x2 * cv + x1 * sv;
}

// ---------------- attention kernel ----------------
constexpr int TQ   = 32;            // query positions per block
constexpr int TK   = 64;            // keys per smem tile
constexpr int ROWS = TQ * G_;       // 128 q-rows (row = qi*4 + g)

constexpr int QSTR = 132;           // padded strides (floats)
constexpr int KSTR = 132;
constexpr int VSTR = 128;
constexpr int PSTR = 65;

constexpr int SM_Q = 0;
constexpr int SM_K = SM_Q + ROWS * QSTR;
constexpr int SM_V = SM_K + TK   * KSTR;
constexpr int SM_P = SM_V + TK   * VSTR;
constexpr int SM_M = SM_P + ROWS * PSTR;
constexpr int SM_L = SM_M + ROWS;
constexpr int SM_A = SM_L + ROWS;
constexpr int SMEM_FLOATS = SM_A + ROWS;
constexpr int SMEM_BYTES  = SMEM_FLOATS * 4;   // 168960 B

__global__ void __launch_bounds__(256, 1)
attn_kernel(const float* __restrict__ value, float* __restrict__ out) {
    extern __shared__ float sm[];
    float* Qs = sm + SM_Q;
    float* Ks = sm + SM_K;
    float* Vs = sm + SM_V;
    float* Ps = sm + SM_P;
    float* Ms = sm + SM_M;
    float* Ls = sm + SM_L;
    float* As = sm + SM_A;

    const int tid = threadIdx.x;
    const int bid = blockIdx.x;
    const int qt = bid & 63;          // S_/TQ = 64
    const int hk = (bid >> 6) & 7;    // HK_ = 8
    const int b  = bid >> 9;
    const int q0 = qt * TQ;

    const float scale = 0.08838834764831845f;   // 1/sqrt(128)

    // ---- load Q tile (scale folded in): 128 rows x 128 d ----
    for (int i = tid; i < ROWS * 32; i += 256) {
        int r = i >> 5, dd = i & 31;
        int qi = r >> 2, g = r & 3;
        float4 qv = *(const float4*)&g_qrope[
            (((size_t)(b * S_ + q0 + qi) * HQ_) + hk * G_ + g) * D_ + dd * 4];
        qv.x *= scale; qv.y *= scale; qv.z *= scale; qv.w *= scale;
        *(float4*)&Qs[r * QSTR + dd * 4] = qv;
    }
    if (tid < ROWS) { Ms[tid] = -1e30f; Ls[tid] = 0.f; }

    // packed output accumulators: 4 rows x 16 d (8 pairs)
    u64 o2[4][8];
    #pragma unroll
    for (int r = 0; r < 4; r++)
        #pragma unroll
        for (int m = 0; m < 8; m++) o2[r][m] = 0ull;

    const int rg = tid >> 3;   // row-group 0..31 (rows rg*4..rg*4+3; qi == rg)
    const int lg = tid & 7;    // key-group (QK) / d-group (PV)

    const int imax = q0 + TQ - 1;
    int lo = q0 - (W_ - 1); if (lo < 0) lo = 0;
    const int kt0 = lo / TK, kt1 = imax / TK;

    for (int kt = kt0; kt <= kt1; ++kt) {
        const int k0 = kt * TK;
        __syncthreads();   // protect K/V/P smem from previous iteration's readers
        // ---- load K,V tile (coalesced) ----
        for (int i = tid; i < TK * 32; i += 256) {
            int kk = i >> 5, dd = i & 31;
            int j = k0 + kk;
            size_t kb = (((size_t)(b * S_ + j) * HK_) + hk) * D_ + dd * 4;
            *(float4*)&Ks[kk * KSTR + dd * 4] = *(const float4*)&g_krope[kb];
            *(float4*)&Vs[kk * VSTR + dd * 4] = *(const float4*)&value[kb];
        }
        __syncthreads();

        // ---- QK^T: thread owns 4 q-rows x 8 keys, packed over d ----
        u64 s2[4][8];
        #pragma unroll
        for (int r = 0; r < 4; r++)
            #pragma unroll
            for (int c = 0; c < 8; c++) s2[r][c] = 0ull;

        for (int dd = 0; dd < 32; ++dd) {
            ulonglong2 qv[4];
            #pragma unroll
            for (int r = 0; r < 4; r++)
                qv[r] = *(const ulonglong2*)&Qs[(rg * 4 + r) * QSTR + dd * 4];
            #pragma unroll
            for (int c = 0; c < 8; c++) {
                ulonglong2 kv = *(const ulonglong2*)&Ks[(lg + 8 * c) * KSTR + dd * 4];
                #pragma unroll
                for (int r = 0; r < 4; r++) {
                    s2[r][c] = ffma2(qv[r].x, kv.x, s2[r][c]);
                    s2[r][c] = ffma2(qv[r].y, kv.y, s2[r][c]);
                }
            }
        }
        #pragma unroll
        for (int r = 0; r < 4; r++)
            #pragma unroll
            for (int c = 0; c < 8; c++) {
                float2 f = unpack2(s2[r][c]);
                Ps[(rg * 4 + r) * PSTR + lg + 8 * c] = f.x + f.y;
            }
        __syncthreads();

        // ---- online-softmax row pass (mask recomputed) ----
        if (tid < ROWS) {
            int i_abs = q0 + (tid >> 2);
            int jlo = i_abs - (W_ - 1) - k0; if (jlo < 0) jlo = 0;
            int jhi = i_abs - k0;            if (jhi > TK - 1) jhi = TK - 1;
            float mo = Ms[tid];
            float mx = mo;
            for (int kk2 = jlo; kk2 <= jhi; ++kk2)
                mx = fmaxf(mx, Ps[tid * PSTR + kk2]);
            float alpha = __expf(mo - mx);
            float l = Ls[tid] * alpha;
            for (int kk2 = 0; kk2 < TK; ++kk2) {
                float p = 0.f;
                if (kk2 >= jlo && kk2 <= jhi)
                    p = __expf(Ps[tid * PSTR + kk2] - mx);
                Ps[tid * PSTR + kk2] = p;
                l += p;
            }
            Ms[tid] = mx; Ls[tid] = l; As[tid] = alpha;
        }
        __syncthreads();

        // ---- rescale acc, then P@V (packed over d) ----
        #pragma unroll
        for (int r = 0; r < 4; r++) {
            u64 al2 = pack2(As[rg * 4 + r]);
            #pragma unroll
            for (int m = 0; m < 8; m++) o2[r][m] = fmul2(o2[r][m], al2);
        }
        for (int kk2 = 0; kk2 < TK; ++kk2) {
            u64 p2[4];
            #pragma unroll
            for (int r = 0; r < 4; r++)
                p2[r] = pack2(Ps[(rg * 4 + r) * PSTR + kk2]);
            #pragma unroll
            for (int i2 = 0; i2 < 4; i2++) {
                ulonglong2 vv = *(const ulonglong2*)&Vs[kk2 * VSTR + (lg + 8 * i2) * 4];
                #pragma unroll
                for (int r = 0; r < 4; r++) {
                    o2[r][2 * i2]     = ffma2(p2[r], vv.x, o2[r][2 * i2]);
                    o2[r][2 * i2 + 1] = ffma2(p2[r], vv.y, o2[r][2 * i2 + 1]);
                }
            }
        }
    }

    // ---- epilogue ----
    #pragma unroll
    for (int r = 0; r < 4; r++) {
        int row = rg * 4 + r;
        float invl = 1.f / Ls[row];
        int qi = row >> 2, g = row & 3;
        float* op = out + ((size_t)(b * S_ + q0 + qi) * (HQ_ * D_))
                        + (size_t)(hk * G_ + g) * D_;
        #pragma unroll
        for (int i2 = 0; i2 < 4; i2++) {
            float2 a = unpack2(o2[r][2 * i2]);
            float2 bq = unpack2(o2[r][2 * i2 + 1]);
            float4 o;
            o.x = a.x * invl;  o.y = a.y * invl;
            o.z = bq.x * invl; o.w = bq.y * invl;
            *(float4*)&op[(lg + 8 * i2) * 4] = o;
        }
    }
}

// ---------------- launcher ----------------
extern "C" void kernel_launch(void* const* d_in, const int* in_sizes, int n_in,
                              void* d_out, int out_size) {
    const float* q  = (const float*)d_in[0];
    const float* k  = (const float*)d_in[1];
    const float* v  = (const float*)d_in[2];
    const int*   ps = (const int*)d_in[3];
    float* out = (float*)d_out;

    int total = NTOK * HQ_ * (D_ / 2) + NTOK * HK_ * (D_ / 2);
    rope_kernel<<<(total + 255) / 256, 256>>>(q, k, ps);

    cudaFuncSetAttribute(attn_kernel,
                         cudaFuncAttributeMaxDynamicSharedMemorySize, SMEM_BYTES);
    int nblk = B_ * HK_ * (S_ / TQ);   // 1024
    attn_kernel<<<nblk, 256, SMEM_BYTES>>>(v, out);
}